// round 1
// baseline (speedup 1.0000x reference)
#include <cuda_runtime.h>
#include <math_constants.h>

#define BS          32
#define NUM_GT      64
#define NUM_PRIORS  8400
#define NUM_CLASSES 80
#define TOPK        9

// output layout (float32, concat of returned tuple)
#define OFF_L 0
#define OFF_B (BS*NUM_PRIORS)                       // 268800
#define OFF_S (OFF_B + BS*NUM_PRIORS*4)             // 1344000
#define OFF_F (OFF_S + BS*NUM_PRIORS*NUM_CLASSES)   // 22848000

__device__ int g_fg[BS*NUM_PRIORS];
__device__ int g_firstg[BS*NUM_PRIORS];

__global__ void k_init() {
  int i = blockIdx.x*blockDim.x + threadIdx.x;
  if (i < BS*NUM_PRIORS) { g_fg[i] = 0; g_firstg[i] = 1 << 30; }
}

// One block = (batch, 8 gts); one warp per gt. Prior centers cached in smem.
__global__ __launch_bounds__(256) void k_select(
    const float4* __restrict__ gt_bboxes,
    const float*  __restrict__ pad_flag,
    const float4* __restrict__ priors)
{
  extern __shared__ float2 sc[];   // prior centers, 8400 * 8B
  const int b  = blockIdx.x >> 3;
  const int g0 = (blockIdx.x & 7) << 3;

  for (int p = threadIdx.x; p < NUM_PRIORS; p += 256) {
    float4 pr = priors[p];
    float hx = 2.5f*pr.z, hy = 2.5f*pr.w;
    float x1 = pr.x - hx, x2 = pr.x + hx;
    float y1 = pr.y - hy, y2 = pr.y + hy;
    sc[p] = make_float2((x1 + x2)*0.5f, (y1 + y2)*0.5f);  // match reference rounding
  }
  __syncthreads();

  const int lane = threadIdx.x & 31;
  const int g    = g0 + (threadIdx.x >> 5);
  const float4 G = gt_bboxes[b*NUM_GT + g];
  const float gcx = (G.x + G.z)*0.5f, gcy = (G.y + G.w)*0.5f;
  const float garea = (G.z - G.x)*(G.w - G.y);
  const bool  pad = pad_flag[b*NUM_GT + g] > 0.f;

  int mycand = -1;   // lane c (<27) holds candidate #c

  const int lst[3] = {0, 6400, 8000};
  const int lln[3] = {6400, 1600, 400};
  #pragma unroll
  for (int l = 0; l < 3; l++) {
    // per-lane sorted-ascending (dist^2, idx) top-9 over strided slice
    float d9[TOPK]; int p9[TOPK];
    #pragma unroll
    for (int t = 0; t < TOPK; t++) { d9[t] = CUDART_INF_F; p9[t] = 0x7fffffff; }
    const int st = lst[l], len = lln[l];
    for (int j = lane; j < len; j += 32) {
      float2 c = sc[st + j];
      float dx = gcx - c.x, dy = gcy - c.y;
      float d  = fmaf(dx, dx, dy*dy);
      if (d < d9[TOPK-1]) {          // strict: preserves lowest-index on ties
        int pos = TOPK-1;
        #pragma unroll
        for (int t = TOPK-2; t >= 0; t--) {
          if (d < d9[t]) { d9[t+1] = d9[t]; p9[t+1] = p9[t]; pos = t; }
        }
        d9[pos] = d; p9[pos] = st + j;
      }
    }
    // merge 32 sorted lists: 9 rounds of lexicographic warp arg-min
    for (int r = 0; r < TOPK; r++) {
      float bd = d9[0]; int bp = p9[0]; int bl = lane;
      #pragma unroll
      for (int off = 16; off; off >>= 1) {
        float od = __shfl_xor_sync(0xffffffffu, bd, off);
        int   op = __shfl_xor_sync(0xffffffffu, bp, off);
        int   ol = __shfl_xor_sync(0xffffffffu, bl, off);
        if (od < bd || (od == bd && op < bp)) { bd = od; bp = op; bl = ol; }
      }
      if (lane == l*TOPK + r) mycand = bp;
      if (lane == bl) {            // winner pops its head
        #pragma unroll
        for (int t = 0; t < TOPK-1; t++) { d9[t] = d9[t+1]; p9[t] = p9[t+1]; }
        d9[TOPK-1] = CUDART_INF_F; p9[TOPK-1] = 0x7fffffff;
      }
    }
  }

  // candidate overlap (gt vs 5*stride prior cell), union clamped to 1e-6
  float o = 0.f, px = 0.f, py = 0.f;
  const bool valid = (mycand >= 0);
  if (valid) {
    float4 pr = priors[mycand];
    float hx = 2.5f*pr.z, hy = 2.5f*pr.w;
    float x1 = pr.x - hx, x2 = pr.x + hx, y1 = pr.y - hy, y2 = pr.y + hy;
    px = (x1 + x2)*0.5f; py = (y1 + y2)*0.5f;
    float iw = fmaxf(fminf(G.z, x2) - fmaxf(G.x, x1), 0.f);
    float ih = fmaxf(fminf(G.w, y2) - fmaxf(G.y, y1), 0.f);
    float inter = iw*ih;
    float pa = (x2 - x1)*(y2 - y1);
    o = inter / fmaxf(garea + pa - inter, 1e-6f);
  }
  // thr = mean + std(ddof=1) over the 27 candidate overlaps
  float s = o;
  #pragma unroll
  for (int off = 16; off; off >>= 1) s += __shfl_xor_sync(0xffffffffu, s, off);
  float mean = s / 27.f;
  float v = valid ? (o - mean)*(o - mean) : 0.f;
  #pragma unroll
  for (int off = 16; off; off >>= 1) v += __shfl_xor_sync(0xffffffffu, v, off);
  float thr = mean + sqrtf(v / 26.f);

  if (valid && pad && o > thr) {
    float m = fminf(fminf(px - G.x, py - G.y), fminf(G.z - px, G.w - py));
    if (m > 1e-9f) {   // prior center strictly inside gt
      int key = b*NUM_PRIORS + mycand;
      atomicAdd(&g_fg[key], 1);
      atomicMin(&g_firstg[key], g);
    }
  }
}

#define KP 48    // priors per block
#define KT 192   // threads per block

__global__ __launch_bounds__(KT) void k_out(
    const float4* __restrict__ gt_bboxes,
    const int*    __restrict__ gt_labels,
    const float4* __restrict__ pred,
    const float4* __restrict__ priors,
    float* __restrict__ out)
{
  __shared__ float4 sgt[NUM_GT];
  __shared__ int    slab[NUM_GT];
  __shared__ int    scol[KP];
  __shared__ float  sval[KP];

  const int bpb = NUM_PRIORS / KP;          // 175
  const int b   = blockIdx.x / bpb;
  const int p0  = (blockIdx.x % bpb) * KP;
  const int tid = threadIdx.x;

  if (tid < NUM_GT) {
    sgt[tid]  = gt_bboxes[b*NUM_GT + tid];
    slab[tid] = gt_labels[b*NUM_GT + tid];
  }
  __syncthreads();

  if (tid < KP) {
    const int p   = p0 + tid;
    const int key = b*NUM_PRIORS + p;
    const int fg  = g_fg[key];
    int gi = 0;
    if (fg == 1) {
      gi = g_firstg[key];
    } else if (fg > 1) {
      // resolve multi-claimed prior: argmax over ALL gts of gt-vs-cell IoU (first max)
      float4 pr = priors[p];
      float hx = 2.5f*pr.z, hy = 2.5f*pr.w;
      float x1 = pr.x - hx, x2 = pr.x + hx, y1 = pr.y - hy, y2 = pr.y + hy;
      float pa = (x2 - x1)*(y2 - y1);
      float best = -1.f;
      for (int gg = 0; gg < NUM_GT; gg++) {
        float4 T = sgt[gg];
        float iw = fmaxf(fminf(T.z, x2) - fmaxf(T.x, x1), 0.f);
        float ih = fmaxf(fminf(T.w, y2) - fmaxf(T.y, y1), 0.f);
        float inter = iw*ih;
        float ga = (T.z - T.x)*(T.w - T.y);
        float ov = inter / fmaxf(ga + pa - inter, 1e-6f);
        if (ov > best) { best = ov; gi = gg; }
      }
    }
    float4 T = sgt[gi];
    float labelv, fgm; int col = -1; float iouv = 0.f;
    if (fg > 0) {
      int lab = slab[gi];
      labelv = (float)lab; col = lab; fgm = 1.f;
      // score weight = IoU(gt, pred), union + 1e-9
      float4 P = pred[b*NUM_PRIORS + p];
      float iw = fmaxf(fminf(T.z, P.z) - fmaxf(T.x, P.x), 0.f);
      float ih = fmaxf(fminf(T.w, P.w) - fmaxf(T.y, P.y), 0.f);
      float inter = iw*ih;
      float ga = (T.z - T.x)*(T.w - T.y);
      float pa = (P.z - P.x)*(P.w - P.y);
      iouv = inter / (ga + pa - inter + 1e-9f);
    } else {
      labelv = (float)NUM_CLASSES; fgm = 0.f;   // background; bbox = gt[b][0]
    }
    out[OFF_L + key] = labelv;
    ((float4*)out)[(OFF_B >> 2) + key] = T;
    out[OFF_F + key] = fgm;
    scol[tid] = col; sval[tid] = iouv;
  }
  __syncthreads();

  // coalesced float4 score-slab write (zeros + inline scatter of the one nonzero)
  const int NQ = KP * (NUM_CLASSES/4);   // 960 float4 per block
  float4* sco = (float4*)out + (OFF_S >> 2) + (size_t)(b*NUM_PRIORS + p0)*(NUM_CLASSES/4);
  for (int i = tid; i < NQ; i += KT) {
    int lp = i / (NUM_CLASSES/4);
    int c0 = (i % (NUM_CLASSES/4)) * 4;
    int cl = scol[lp];
    float vv = sval[lp];
    float4 r;
    r.x = (cl == c0    ) ? vv : 0.f;
    r.y = (cl == c0 + 1) ? vv : 0.f;
    r.z = (cl == c0 + 2) ? vv : 0.f;
    r.w = (cl == c0 + 3) ? vv : 0.f;
    sco[i] = r;
  }
}

extern "C" void kernel_launch(void* const* d_in, const int* in_sizes, int n_in,
                              void* d_out, int out_size)
{
  const float4* pred   = (const float4*)d_in[0];
  const float4* priors = (const float4*)d_in[1];
  const int*    gtl    = (const int*)d_in[2];
  const float4* gtb    = (const float4*)d_in[3];
  const float*  pad    = (const float*)d_in[4];
  float* out = (float*)d_out;

  cudaFuncSetAttribute(k_select, cudaFuncAttributeMaxDynamicSharedMemorySize,
                       NUM_PRIORS * (int)sizeof(float2));

  k_init<<<(BS*NUM_PRIORS + 255)/256, 256>>>();
  k_select<<<BS*8, 256, NUM_PRIORS * sizeof(float2)>>>(gtb, pad, priors);
  k_out<<<BS*(NUM_PRIORS/KP), KT>>>(gtb, gtl, pred, priors, out);
}

// round 2
// speedup vs baseline: 2.7519x; 2.7519x over previous
#include <cuda_runtime.h>
#include <math_constants.h>

#define BS          32
#define NUM_GT      64
#define NUM_PRIORS  8400
#define NUM_CLASSES 80
#define TOPK        9

// output layout (float32, concat of returned tuple)
#define OFF_L 0
#define OFF_B (BS*NUM_PRIORS)                       // 268800
#define OFF_S (OFF_B + BS*NUM_PRIORS*4)             // 1344000
#define OFF_F (OFF_S + BS*NUM_PRIORS*NUM_CLASSES)   // 22848000

// static zero-init; k_out resets after reading so every graph replay sees zeros.
__device__ int g_fg[BS*NUM_PRIORS];     // claim count
__device__ int g_bn[BS*NUM_PRIORS];     // max over claims of (63-g)  => min g = 63 - g_bn

// One block = (batch, 8 gts); one warp per gt. Prior centers cached in smem.
__global__ __launch_bounds__(256) void k_select(
    const float4* __restrict__ gt_bboxes,
    const float*  __restrict__ pad_flag,
    const float4* __restrict__ priors)
{
  extern __shared__ float2 sc[];   // prior centers, 8400 * 8B
  const int b  = blockIdx.x >> 3;
  const int g0 = (blockIdx.x & 7) << 3;

  for (int p = threadIdx.x; p < NUM_PRIORS; p += 256) {
    float4 pr = priors[p];
    float hx = 2.5f*pr.z, hy = 2.5f*pr.w;
    float x1 = pr.x - hx, x2 = pr.x + hx;
    float y1 = pr.y - hy, y2 = pr.y + hy;
    sc[p] = make_float2((x1 + x2)*0.5f, (y1 + y2)*0.5f);  // match reference rounding
  }
  __syncthreads();

  const int lane = threadIdx.x & 31;
  const int g    = g0 + (threadIdx.x >> 5);
  const float4 G = gt_bboxes[b*NUM_GT + g];
  const float gcx = (G.x + G.z)*0.5f, gcy = (G.y + G.w)*0.5f;
  const float garea = (G.z - G.x)*(G.w - G.y);
  const bool  pad = pad_flag[b*NUM_GT + g] > 0.f;

  int mycand = -1;   // lane c (<27) holds candidate #c

  const int lst[3] = {0, 6400, 8000};
  const int lln[3] = {6400, 1600, 400};
  #pragma unroll
  for (int l = 0; l < 3; l++) {
    // per-lane sorted-ascending (dist^2, idx) top-9 over strided slice.
    // Fully register-resident: constant-index predicated insertion only.
    float d9[TOPK]; int p9[TOPK];
    #pragma unroll
    for (int t = 0; t < TOPK; t++) { d9[t] = CUDART_INF_F; p9[t] = 0x7fffffff; }
    const int st = lst[l], len = lln[l];
    for (int j = lane; j < len; j += 32) {
      float2 c = sc[st + j];
      float dx = gcx - c.x, dy = gcy - c.y;
      float d  = fmaf(dx, dx, dy*dy);
      if (d < d9[TOPK-1]) {
        const int pj = st + j;
        // descending predicated shift/insert; strict < keeps top_k's
        // lowest-index-first tie order (new equal elements land below).
        #pragma unroll
        for (int t = TOPK-1; t > 0; t--) {
          bool sh = d < d9[t-1];
          bool wr = d < d9[t];
          float nd = sh ? d9[t-1] : d;
          int   np = sh ? p9[t-1] : pj;
          if (wr) { d9[t] = nd; p9[t] = np; }
        }
        if (d < d9[0]) { d9[0] = d; p9[0] = pj; }
      }
    }
    // merge 32 sorted lists: 9 rounds of lexicographic warp arg-min
    for (int r = 0; r < TOPK; r++) {
      float bd = d9[0]; int bp = p9[0]; int bl = lane;
      #pragma unroll
      for (int off = 16; off; off >>= 1) {
        float od = __shfl_xor_sync(0xffffffffu, bd, off);
        int   op = __shfl_xor_sync(0xffffffffu, bp, off);
        int   ol = __shfl_xor_sync(0xffffffffu, bl, off);
        if (od < bd || (od == bd && op < bp)) { bd = od; bp = op; bl = ol; }
      }
      if (lane == l*TOPK + r) mycand = bp;
      if (lane == bl) {            // winner pops its head (constant indices)
        #pragma unroll
        for (int t = 0; t < TOPK-1; t++) { d9[t] = d9[t+1]; p9[t] = p9[t+1]; }
        d9[TOPK-1] = CUDART_INF_F; p9[TOPK-1] = 0x7fffffff;
      }
    }
  }

  // candidate overlap (gt vs 5*stride prior cell), union clamped to 1e-6
  float o = 0.f, px = 0.f, py = 0.f;
  const bool valid = (mycand >= 0);
  if (valid) {
    float4 pr = priors[mycand];
    float hx = 2.5f*pr.z, hy = 2.5f*pr.w;
    float x1 = pr.x - hx, x2 = pr.x + hx, y1 = pr.y - hy, y2 = pr.y + hy;
    px = (x1 + x2)*0.5f; py = (y1 + y2)*0.5f;
    float iw = fmaxf(fminf(G.z, x2) - fmaxf(G.x, x1), 0.f);
    float ih = fmaxf(fminf(G.w, y2) - fmaxf(G.y, y1), 0.f);
    float inter = iw*ih;
    float pa = (x2 - x1)*(y2 - y1);
    o = inter / fmaxf(garea + pa - inter, 1e-6f);
  }
  // thr = mean + std(ddof=1) over the 27 candidate overlaps
  float s = o;
  #pragma unroll
  for (int off = 16; off; off >>= 1) s += __shfl_xor_sync(0xffffffffu, s, off);
  float mean = s / 27.f;
  float v = valid ? (o - mean)*(o - mean) : 0.f;
  #pragma unroll
  for (int off = 16; off; off >>= 1) v += __shfl_xor_sync(0xffffffffu, v, off);
  float thr = mean + sqrtf(v / 26.f);

  if (valid && pad && o > thr) {
    float m = fminf(fminf(px - G.x, py - G.y), fminf(G.z - px, G.w - py));
    if (m > 1e-9f) {   // prior center strictly inside gt
      int key = b*NUM_PRIORS + mycand;
      atomicAdd(&g_fg[key], 1);
      atomicMax(&g_bn[key], 63 - g);
    }
  }
}

#define KP 48    // priors per block
#define KT 192   // threads per block

__global__ __launch_bounds__(KT) void k_out(
    const float4* __restrict__ gt_bboxes,
    const int*    __restrict__ gt_labels,
    const float4* __restrict__ pred,
    const float4* __restrict__ priors,
    float* __restrict__ out)
{
  __shared__ float4 sgt[NUM_GT];
  __shared__ int    slab[NUM_GT];
  __shared__ int    scol[KP];
  __shared__ float  sval[KP];

  const int bpb = NUM_PRIORS / KP;          // 175
  const int b   = blockIdx.x / bpb;
  const int p0  = (blockIdx.x % bpb) * KP;
  const int tid = threadIdx.x;

  if (tid < NUM_GT) {
    sgt[tid]  = gt_bboxes[b*NUM_GT + tid];
    slab[tid] = gt_labels[b*NUM_GT + tid];
  }
  __syncthreads();

  if (tid < KP) {
    const int p   = p0 + tid;
    const int key = b*NUM_PRIORS + p;
    const int fg  = g_fg[key];
    const int bn  = g_bn[key];
    // reset for the next graph replay (deterministic: every key covered once)
    g_fg[key] = 0;
    g_bn[key] = 0;
    int gi = 0;
    if (fg == 1) {
      gi = 63 - bn;
    } else if (fg > 1) {
      // resolve multi-claimed prior: argmax over ALL gts of gt-vs-cell IoU (first max)
      float4 pr = priors[p];
      float hx = 2.5f*pr.z, hy = 2.5f*pr.w;
      float x1 = pr.x - hx, x2 = pr.x + hx, y1 = pr.y - hy, y2 = pr.y + hy;
      float pa = (x2 - x1)*(y2 - y1);
      float best = -1.f;
      for (int gg = 0; gg < NUM_GT; gg++) {
        float4 T = sgt[gg];
        float iw = fmaxf(fminf(T.z, x2) - fmaxf(T.x, x1), 0.f);
        float ih = fmaxf(fminf(T.w, y2) - fmaxf(T.y, y1), 0.f);
        float inter = iw*ih;
        float ga = (T.z - T.x)*(T.w - T.y);
        float ov = inter / fmaxf(ga + pa - inter, 1e-6f);
        if (ov > best) { best = ov; gi = gg; }
      }
    }
    float4 T = sgt[gi];
    float labelv, fgm; int col = -1; float iouv = 0.f;
    if (fg > 0) {
      int lab = slab[gi];
      labelv = (float)lab; col = lab; fgm = 1.f;
      // score weight = IoU(gt, pred), union + 1e-9
      float4 P = pred[b*NUM_PRIORS + p];
      float iw = fmaxf(fminf(T.z, P.z) - fmaxf(T.x, P.x), 0.f);
      float ih = fmaxf(fminf(T.w, P.w) - fmaxf(T.y, P.y), 0.f);
      float inter = iw*ih;
      float ga = (T.z - T.x)*(T.w - T.y);
      float pa = (P.z - P.x)*(P.w - P.y);
      iouv = inter / (ga + pa - inter + 1e-9f);
    } else {
      labelv = (float)NUM_CLASSES; fgm = 0.f;   // background; bbox = gt[b][0]
    }
    out[OFF_L + key] = labelv;
    ((float4*)out)[(OFF_B >> 2) + key] = T;
    out[OFF_F + key] = fgm;
    scol[tid] = col; sval[tid] = iouv;
  }
  __syncthreads();

  // coalesced float4 score-slab write (zeros + inline scatter of the one nonzero)
  const int NQ = KP * (NUM_CLASSES/4);   // 960 float4 per block
  float4* sco = (float4*)out + (OFF_S >> 2) + (size_t)(b*NUM_PRIORS + p0)*(NUM_CLASSES/4);
  for (int i = tid; i < NQ; i += KT) {
    int lp = i / (NUM_CLASSES/4);
    int c0 = (i % (NUM_CLASSES/4)) * 4;
    int cl = scol[lp];
    float vv = sval[lp];
    float4 r;
    r.x = (cl == c0    ) ? vv : 0.f;
    r.y = (cl == c0 + 1) ? vv : 0.f;
    r.z = (cl == c0 + 2) ? vv : 0.f;
    r.w = (cl == c0 + 3) ? vv : 0.f;
    sco[i] = r;
  }
}

extern "C" void kernel_launch(void* const* d_in, const int* in_sizes, int n_in,
                              void* d_out, int out_size)
{
  const float4* pred   = (const float4*)d_in[0];
  const float4* priors = (const float4*)d_in[1];
  const int*    gtl    = (const int*)d_in[2];
  const float4* gtb    = (const float4*)d_in[3];
  const float*  pad    = (const float*)d_in[4];
  float* out = (float*)d_out;

  cudaFuncSetAttribute(k_select, cudaFuncAttributeMaxDynamicSharedMemorySize,
                       NUM_PRIORS * (int)sizeof(float2));

  k_select<<<BS*8, 256, NUM_PRIORS * sizeof(float2)>>>(gtb, pad, priors);
  k_out<<<BS*(NUM_PRIORS/KP), KT>>>(gtb, gtl, pred, priors, out);
}